// round 17
// baseline (speedup 1.0000x reference)
#include <cuda_runtime.h>
#include <cuda_fp16.h>
#include <cstdint>

// Problem constants
#define N_NODES  100000
#define N_EDGES  500000
#define IN_FEATS 256
#define HIDDEN   64
#define NSM      148

// Fused per-node activations in fp16:
//   g_AB2[node][0..31]  = half2 pairs of A = h@W1_top + b1   (cols 0..63)
//   g_AB2[node][32..63] = half2 pairs of B = h@W1_bot        (cols 64..127)
__device__ __half2 g_AB2[(size_t)N_NODES * 64];

#define BP   264        // B pitch in fp16 (row = 528 B; 132 words % 32 == 4 -> LDSM conflict-free)
#define APB  144        // A pitch in bytes (72 fp16; 36 words % 32 == 4 -> LDSM conflict-free)

// smem byte offsets: B hi | A buf0 | A buf1 | b1
#define SM_BH   0
#define SM_A0   67584
#define SM_A1   86016
#define SM_B1   104448
#define SMEM_TOTAL 104704

static __device__ __forceinline__ uint32_t smem_u32(const void* p) {
    uint32_t a;
    asm("{ .reg .u64 t; cvta.to.shared.u64 t, %1; cvt.u32.u64 %0, t; }" : "=r"(a) : "l"(p));
    return a;
}

// Pair-scope named barrier: 2 warps (64 threads), id = pair+1 (0 reserved).
static __device__ __forceinline__ void bar_pair(int id) {
    asm volatile("bar.sync %0, %1;" :: "r"(id), "r"(64) : "memory");
}

static __device__ __forceinline__ void ldsm4(uint32_t* r, uint32_t addr) {
    asm volatile("ldmatrix.sync.aligned.m8n8.x4.shared.b16 {%0,%1,%2,%3}, [%4];"
        : "=r"(r[0]), "=r"(r[1]), "=r"(r[2]), "=r"(r[3]) : "r"(addr));
}

// fp16 warp MMA m16n8k16 with FP16 accumulators (2x rate hypothesis: rt 16 vs 32).
// D (+= C) kept in 2 b32 regs (4 halves), zero-initialized per burst.
static __device__ __forceinline__ void mma16816_h(uint32_t* d,
        const uint32_t* a, uint32_t b0, uint32_t b1) {
    asm volatile(
        "mma.sync.aligned.m16n8k16.row.col.f16.f16.f16.f16 "
        "{%0,%1}, {%2,%3,%4,%5}, {%6,%7}, {%0,%1};"
        : "+r"(d[0]), "+r"(d[1])
        : "r"(a[0]), "r"(a[1]), "r"(a[2]), "r"(a[3]), "r"(b0), "r"(b1));
}

// ---------------------------------------------------------------------------
// Kernel 1: PERSISTENT tensor-core node GEMM, fp16 inputs, fp16 MMA accum
// promoted to fp32 master accumulators every 2 k-steps (k=32).
// Calibrated error model: +4.0e-4 incoherent -> total ~6.2e-4 (<1e-3).
// 8 warps (4M x 2N), warp tile 32x64; K=256 as 4 chunks of 64; pair-local A
// staging with bar.sync(wm+1,64); double-buffered A; cross-tile prefetch.
// 1 CTA/SM (255-reg budget: fp32 masters + fp16 burst accs, no spills).
// ---------------------------------------------------------------------------
__global__ __launch_bounds__(256, 1)
void node_gemm_mma(const float4* __restrict__ h4, const float* __restrict__ W1,
                   const float* __restrict__ b1, int n_nodes, int n_tiles)
{
    extern __shared__ char smem[];
    const uint32_t sb = smem_u32(smem);
    float* b1s = (float*)(smem + SM_B1);

    const int tid  = threadIdx.x;
    const int wid  = tid >> 5, lane = tid & 31;
    const int gid  = lane >> 2, tig = lane & 3;
    const int wm   = wid >> 1, wn = wid & 1;
    const int bar_id = wm + 1;

    // Build B image once: B[n][k] = Wcat[k][n] in fp16.
    {
        unsigned short* BH = (unsigned short*)(smem + SM_BH);
        #pragma unroll 8
        for (int i = tid; i < 32768; i += 256) {
            int n = i & 127, k = i >> 7;
            float x = (n < 64) ? W1[k * 64 + n] : W1[(256 + k) * 64 + (n - 64)];
            BH[n * BP + k] = __half_as_ushort(__float2half_rn(x));
        }
    }
    if (tid < 64) b1s[tid] = b1[tid];
    __syncthreads();   // one-time: B + b1 visible to all warps

    // ldmatrix lane addressing.
    const int r8 = lane & 7;
    const uint32_t a_off = (uint32_t)((wm * 32 + (((lane >> 3) & 1) << 3) + r8) * APB
                                      + (((lane >> 4) & 1) << 4));
    const uint32_t b_row = (uint32_t)(wn * 64 + ((lane >> 4) << 3) + r8);
    const uint32_t b_off = b_row * (BP * 2) + (((lane >> 3) & 1) << 4);
    const uint32_t baseBH = sb + SM_BH + b_off;
    const uint32_t abuf[2] = { sb + SM_A0 + a_off, sb + SM_A1 + a_off };

    // Pair-local staging map: pair wm stages rows wm*32..wm*32+31.
    const int wtid   = tid & 63;
    const int s_f4   = wtid & 15;                 // k float4 index 0..15
    const int s_row0 = wm * 32 + (wtid >> 4);     // rows s_row0 + j*4, j=0..7

    // Prologue: stage first tile's chunk 0 into buf0 (pair-local rows).
    if (blockIdx.x < n_tiles) {
        const int node0 = blockIdx.x * 128;
        #pragma unroll
        for (int j = 0; j < 8; j++) {
            int row = s_row0 + j * 4;
            int node = node0 + row;
            float4 v = make_float4(0.f, 0.f, 0.f, 0.f);
            if (node < n_nodes) v = h4[(size_t)node * 64 + s_f4];
            __half2 p0 = __floats2half2_rn(v.x, v.y);
            __half2 p1 = __floats2half2_rn(v.z, v.w);
            *(uint2*)(smem + SM_A0 + row * APB + s_f4 * 8) =
                make_uint2(*(uint32_t*)&p0, *(uint32_t*)&p1);
        }
    }
    bar_pair(bar_id);

    for (int tile = blockIdx.x; tile < n_tiles; tile += gridDim.x) {
        const int node0 = tile * 128;

        float c[2][8][4];
        #pragma unroll
        for (int mm = 0; mm < 2; mm++)
            #pragma unroll
            for (int nn = 0; nn < 8; nn++)
                #pragma unroll
                for (int q = 0; q < 4; q++) c[mm][nn][q] = 0.f;

        #pragma unroll
        for (int chunk = 0; chunk < 4; chunk++) {
            const int buf = chunk & 1;

            // Prefetch target: next chunk, or next tile's chunk 0 (pair rows).
            int pnode0 = node0, pchunk = chunk + 1;
            bool havepf = true;
            if (chunk == 3) {
                int nt = tile + gridDim.x;
                havepf = nt < n_tiles;
                pnode0 = nt * 128;
                pchunk = 0;
            }
            float4 pf[8];
            if (havepf) {
                #pragma unroll
                for (int j = 0; j < 8; j++) {
                    int node = pnode0 + s_row0 + j * 4;
                    pf[j] = make_float4(0.f, 0.f, 0.f, 0.f);
                    if (node < n_nodes)
                        pf[j] = h4[(size_t)node * 64 + pchunk * 16 + s_f4];
                }
            }

            // MMA over this chunk: 2 bursts of 2 k16-steps, fp16 accumulate
            // within burst, promote to fp32 masters after each burst.
            #pragma unroll
            for (int half = 0; half < 2; half++) {
                uint32_t d[2][8][2];
                #pragma unroll
                for (int mm = 0; mm < 2; mm++)
                    #pragma unroll
                    for (int nn = 0; nn < 8; nn++)
                        d[mm][nn][0] = d[mm][nn][1] = 0u;

                #pragma unroll
                for (int kk = 0; kk < 2; kk++) {
                    const int ks = half * 2 + kk;
                    const uint32_t akb = (uint32_t)(ks * 32);
                    const uint32_t bkb = (uint32_t)(chunk * 128 + ks * 32);

                    uint32_t ah[2][4], bh[4][4];
                    ldsm4(ah[0], abuf[buf] + akb);
                    ldsm4(ah[1], abuf[buf] + 16 * APB + akb);
                    #pragma unroll
                    for (int p = 0; p < 4; p++)
                        ldsm4(bh[p], baseBH + (uint32_t)(p * 16 * BP * 2) + bkb);

                    #pragma unroll
                    for (int mm = 0; mm < 2; mm++)
                        #pragma unroll
                        for (int nn = 0; nn < 8; nn++)
                            mma16816_h(d[mm][nn], ah[mm],
                                       bh[nn >> 1][(nn & 1) * 2],
                                       bh[nn >> 1][(nn & 1) * 2 + 1]);
                }

                // Promote burst accumulators to fp32 masters (idle FMA pipe).
                #pragma unroll
                for (int mm = 0; mm < 2; mm++)
                    #pragma unroll
                    for (int nn = 0; nn < 8; nn++) {
                        float2 lo = __half22float2(*(__half2*)&d[mm][nn][0]);
                        float2 hi = __half22float2(*(__half2*)&d[mm][nn][1]);
                        c[mm][nn][0] += lo.x;
                        c[mm][nn][1] += lo.y;
                        c[mm][nn][2] += hi.x;
                        c[mm][nn][3] += hi.y;
                    }
            }

            // Store prefetched rows into the other buffer, pair barrier.
            if (havepf) {
                const int dst = SM_A0 + (1 - buf) * (SM_A1 - SM_A0);
                #pragma unroll
                for (int j = 0; j < 8; j++) {
                    int row = s_row0 + j * 4;
                    __half2 p0 = __floats2half2_rn(pf[j].x, pf[j].y);
                    __half2 p1 = __floats2half2_rn(pf[j].z, pf[j].w);
                    *(uint2*)(smem + dst + row * APB + s_f4 * 8) =
                        make_uint2(*(uint32_t*)&p0, *(uint32_t*)&p1);
                }
                bar_pair(bar_id);
            }
        }

        // Epilogue: fold b1 into cols<64 (warps with wn==0), convert to half2,
        // write g_AB2 rows. Overlaps next-tile chunk-0 ldg latency.
        #pragma unroll
        for (int mm = 0; mm < 2; mm++) {
            #pragma unroll
            for (int nn = 0; nn < 8; nn++) {
                int col = wn * 64 + nn * 8 + tig * 2;
                float bx = 0.f, by = 0.f;
                if (wn == 0) { bx = b1s[col]; by = b1s[col + 1]; }
                int h2i = col >> 1;                 // half2 index within row
                int na = node0 + wm * 32 + mm * 16 + gid;
                if (na < n_nodes)
                    g_AB2[(size_t)na * 64 + h2i] =
                        __floats2half2_rn(c[mm][nn][0] + bx, c[mm][nn][1] + by);
                int nb = na + 8;
                if (nb < n_nodes)
                    g_AB2[(size_t)nb * 64 + h2i] =
                        __floats2half2_rn(c[mm][nn][2] + bx, c[mm][nn][3] + by);
            }
        }
    }
}

// ---------------------------------------------------------------------------
// Kernel 2: per-edge epilogue over fp16 activations. Lane sub=lane&7 owns 8
// hidden channels via ONE uint4 per side; 4 edges per warp-row, 4 rows =
// 16 edges/warp (8 uint4 gathers in flight for L2 latency hiding).
// out[e] = sum_j relu(A[u][j] + B[v][j]) * W2[j] + b2   (fp32 accumulate)
// ---------------------------------------------------------------------------
__global__ __launch_bounds__(256)
void edge_kernel(const int* __restrict__ ei, const float* __restrict__ W2,
                 const float* __restrict__ b2, float* __restrict__ out, int n_edges)
{
    const int lane = threadIdx.x & 31;
    const int sub  = lane & 7;          // channel group within edge
    const int eg   = lane >> 3;         // 0..3: edge within warp-row
    const int w = (blockIdx.x * blockDim.x + threadIdx.x) >> 5;
    const int e0 = w * 16;
    if (e0 >= n_edges) return;

    const float4 w2a = *(const float4*)&W2[sub * 8];
    const float4 w2b = *(const float4*)&W2[sub * 8 + 4];
    const float bias = b2[0];

    int eidx[4];
    uint4 av[4], bv[4];
    #pragma unroll
    for (int r = 0; r < 4; r++) {
        int e = e0 + r * 4 + eg;
        if (e > n_edges - 1) e = n_edges - 1;   // clamp keeps loads batched
        eidx[r] = e;
        int u = ei[e];
        int v = ei[n_edges + e];
        av[r] = *(const uint4*)&g_AB2[(size_t)u * 64 + sub * 4];
        bv[r] = *(const uint4*)&g_AB2[(size_t)v * 64 + 32 + sub * 4];
    }
    #pragma unroll
    for (int r = 0; r < 4; r++) {
        const __half2* ah = (const __half2*)&av[r];
        const __half2* bh = (const __half2*)&bv[r];
        float2 s0 = __half22float2(__hadd2(ah[0], bh[0]));
        float2 s1 = __half22float2(__hadd2(ah[1], bh[1]));
        float2 s2 = __half22float2(__hadd2(ah[2], bh[2]));
        float2 s3 = __half22float2(__hadd2(ah[3], bh[3]));
        float p;
        p  = fmaxf(s0.x, 0.f) * w2a.x;
        p  = fmaf(fmaxf(s0.y, 0.f), w2a.y, p);
        p  = fmaf(fmaxf(s1.x, 0.f), w2a.z, p);
        p  = fmaf(fmaxf(s1.y, 0.f), w2a.w, p);
        p  = fmaf(fmaxf(s2.x, 0.f), w2b.x, p);
        p  = fmaf(fmaxf(s2.y, 0.f), w2b.y, p);
        p  = fmaf(fmaxf(s3.x, 0.f), w2b.z, p);
        p  = fmaf(fmaxf(s3.y, 0.f), w2b.w, p);
        p += __shfl_xor_sync(0xffffffffu, p, 1);
        p += __shfl_xor_sync(0xffffffffu, p, 2);
        p += __shfl_xor_sync(0xffffffffu, p, 4);
        if (sub == 0 && e0 + r * 4 + eg < n_edges) out[eidx[r]] = p + bias;
    }
}

// ---------------------------------------------------------------------------
// Launch. Inputs (metadata order): h, edge_index (int32), W1, b1, W2, b2.
// ---------------------------------------------------------------------------
extern "C" void kernel_launch(void* const* d_in, const int* in_sizes, int n_in,
                              void* d_out, int out_size)
{
    const float* h   = (const float*)d_in[0];
    const int*   ei  = (const int*)d_in[1];
    const float* W1  = (const float*)d_in[2];
    const float* b1  = (const float*)d_in[3];
    const float* W2  = (const float*)d_in[4];
    const float* b2  = (const float*)d_in[5];
    float*       out = (float*)d_out;

    const int n_nodes = in_sizes[0] / IN_FEATS;   // 100000
    const int n_edges = out_size;                 // 500000
    const int n_tiles = (n_nodes + 127) / 128;    // 782

    cudaFuncSetAttribute(node_gemm_mma,
                         cudaFuncAttributeMaxDynamicSharedMemorySize, SMEM_TOTAL);
    int gemm_blocks = n_tiles < NSM ? n_tiles : NSM;
    node_gemm_mma<<<gemm_blocks, 256, SMEM_TOTAL>>>((const float4*)h, W1, b1,
                                                    n_nodes, n_tiles);

    int edge_blocks = (n_edges + 127) / 128;      // 128 edges per 256-thread block
    edge_kernel<<<edge_blocks, 256>>>(ei, W2, b2, out, n_edges);
}